// round 12
// baseline (speedup 1.0000x reference)
#include <cuda_runtime.h>
#include <math.h>

#define H      1024
#define TSTEPS 2048
#define KOUT   64
#define NBLK   128     // = H/8, one block per 8 hidden units
#define NTHR   512     // 16 warps -> 32 gate rows (2 rows per warp)

// Scratch (device globals: no allocation allowed in kernel_launch)
__device__ float g_hs[TSTEPS * H];   // h_t history (consumed by the MLP pass)
// Release-ordered broadcast, ping-pong slots:
//   g_pub[slot][block][4]  : 8 h floats as 4 u64 words (two relaxed 16B stores)
//   g_ptag[slot][block]    : release-stored tag word (tag = step+1)
// Producer: 2x st.relaxed.v2.u64 data, then st.release.gpu.u64 tag -- the
// release orders the data stores. Consumer: thread i polls ONLY producer i's
// tag (relaxed, 2-deep), then fence.acq_rel.gpu + relaxed data loads.
// Poll traffic: 128 thr x 8B per block per sweep = 128KB chip-wide (16x less
// than per-packet tags), so detection RTs ride on a clean L2.
__device__ __align__(16) unsigned long long g_pub[2][NBLK][4];
__device__ unsigned long long g_ptag[2][NBLK];

// ---------- helpers ----------

__device__ __forceinline__ float2 ffma2(float2 a, float2 b, float2 c) {
    unsigned long long ua = *reinterpret_cast<unsigned long long*>(&a);
    unsigned long long ub = *reinterpret_cast<unsigned long long*>(&b);
    unsigned long long uc = *reinterpret_cast<unsigned long long*>(&c);
    unsigned long long ud;
    asm("fma.rn.f32x2 %0, %1, %2, %3;" : "=l"(ud) : "l"(ua), "l"(ub), "l"(uc));
    return *reinterpret_cast<float2*>(&ud);
}

__device__ __forceinline__ unsigned long long ld_relaxed_u64(const unsigned long long* p) {
    unsigned long long v;
    asm volatile("ld.relaxed.gpu.global.u64 %0, [%1];" : "=l"(v) : "l"(p) : "memory");
    return v;
}

__device__ __forceinline__ void ld_relaxed_2u64(const unsigned long long* p,
                                                unsigned long long& a,
                                                unsigned long long& b) {
    asm volatile("ld.relaxed.gpu.global.v2.u64 {%0,%1}, [%2];"
                 : "=l"(a), "=l"(b) : "l"(p) : "memory");
}

__device__ __forceinline__ void st_relaxed_2u64(unsigned long long* p,
                                                unsigned long long a,
                                                unsigned long long b) {
    asm volatile("st.relaxed.gpu.global.v2.u64 [%0], {%1,%2};"
                 :: "l"(p), "l"(a), "l"(b) : "memory");
}

__device__ __forceinline__ void st_release_u64(unsigned long long* p, unsigned long long v) {
    asm volatile("st.release.gpu.global.u64 [%0], %1;" :: "l"(p), "l"(v) : "memory");
}

__device__ __forceinline__ void fence_acq() {
    asm volatile("fence.acq_rel.gpu;" ::: "memory");
}

// MUFU-approx sigmoid/tanh (~1e-6 rel/op). VALIDATED in R10/R11 under the
// strong transport: full 2048-step recurrence at rel_err 2.03e-7.
__device__ __forceinline__ float fsigm(float x) {
    float e, r;
    asm("ex2.approx.f32 %0, %1;" : "=f"(e) : "f"(-1.4426950408889634f * x));
    asm("rcp.approx.f32 %0, %1;" : "=f"(r) : "f"(1.0f + e));
    return r;
}
__device__ __forceinline__ float ftanh(float x) {
    return fmaf(2.0f, fsigm(2.0f * x), -1.0f);
}

// ---------- persistent LSTM recurrence ----------
//
// Block b owns hidden units [8b, 8b+8). Warp w (0..15) computes gate rows
// r0=2w, r1=2w+1 (one gate octet per warp -> uniform nonlinearity per warp).
// Global row R = (r>>3)*H + b*8 + (r&7); gate order i,f,g,o.
// Weights Wc = Wih+Whh in registers (2 rows x 8 float4/thread -- R10 proved
// 4 rows/thread spills; this is the sweet spot).

__global__ void __launch_bounds__(NTHR, 1)
lstm_kernel(const float* __restrict__ z,
            const float* __restrict__ Wih,
            const float* __restrict__ Whh,
            const float* __restrict__ bih,
            const float* __restrict__ bhh)
{
    __shared__ __align__(16) float h_sm[H];
    __shared__ float gates_sm[32];               // post-nonlinearity gates
    __shared__ __align__(16) float hpub_sm[8];   // producer gather buffer

    const int tid = threadIdx.x;
    const int b   = blockIdx.x;
    const int w   = tid >> 5;
    const int l   = tid & 31;
    const int r0  = 2 * w;
    const int r1  = 2 * w + 1;
    const int R0  = (r0 >> 3) * H + b * 8 + (r0 & 7);
    const int R1  = (r1 >> 3) * H + b * 8 + (r1 & 7);
    const bool warp_is_tanh = (w >= 8 && w < 12);   // gate g rows 16..23

    // Stage z into h_sm (input of step 0).
    reinterpret_cast<float2*>(h_sm)[tid] = reinterpret_cast<const float2*>(z)[tid];
    __syncthreads();

    const float4* Wih4 = reinterpret_cast<const float4*>(Wih);
    const float4* Whh4 = reinterpret_cast<const float4*>(Whh);
    const float4* h4   = reinterpret_cast<const float4*>(h_sm);

    // Prologue: load Wih/Whh once; compute step-0 partials with Wih (h0=0),
    // keep Wc = Wih + Whh resident in registers for all later steps.
    float4 wc0[8], wc1[8];
    float2 a0 = make_float2(0.f, 0.f);
    float2 a1 = make_float2(0.f, 0.f);
#pragma unroll
    for (int i = 0; i < 8; i++) {
        const int c0i = R0 * (H / 4) + i * 32 + l;
        const int c1i = R1 * (H / 4) + i * 32 + l;
        float4 wi0 = Wih4[c0i], wh0 = Whh4[c0i];
        float4 wi1 = Wih4[c1i], wh1 = Whh4[c1i];
        float4 hv  = h4[i * 32 + l];
        a0 = ffma2(make_float2(wi0.x, wi0.y), make_float2(hv.x, hv.y), a0);
        a0 = ffma2(make_float2(wi0.z, wi0.w), make_float2(hv.z, hv.w), a0);
        a1 = ffma2(make_float2(wi1.x, wi1.y), make_float2(hv.x, hv.y), a1);
        a1 = ffma2(make_float2(wi1.z, wi1.w), make_float2(hv.z, hv.w), a1);
        wc0[i] = make_float4(wi0.x + wh0.x, wi0.y + wh0.y, wi0.z + wh0.z, wi0.w + wh0.w);
        wc1[i] = make_float4(wi1.x + wh1.x, wi1.y + wh1.y, wi1.z + wh1.z, wi1.w + wh1.w);
    }
    const float bc0 = bih[R0] + bhh[R0];
    const float bc1 = bih[R1] + bhh[R1];

    float c = 0.0f;   // cell state: live only in warp 0, lanes 0..7

    for (int t = 0; t < TSTEPS; t++) {
        if (t > 0) {
            // Transport in: thread i<128 owns producer i. Poll ONLY its tag
            // word (2-deep relaxed), then acquire-fence + fetch 32B data.
            if (tid < NBLK) {
                const int slot = (t - 1) & 1;
                const unsigned long long want = (unsigned long long)t;
                const unsigned long long* tp = &g_ptag[slot][tid];
                unsigned long long t0, t1;
                for (;;) {
                    t0 = ld_relaxed_u64(tp);
                    t1 = ld_relaxed_u64(tp);
                    if (t0 == want || t1 == want) break;
                }
                fence_acq();   // upgrade observed release-tag to acquire
                const unsigned long long* dp = g_pub[slot][tid];
                unsigned long long d0, d1, d2, d3;
                ld_relaxed_2u64(dp,     d0, d1);
                ld_relaxed_2u64(dp + 2, d2, d3);
                unsigned long long* hdst =
                    reinterpret_cast<unsigned long long*>(h_sm) + 4 * tid;
                hdst[0] = d0; hdst[1] = d1; hdst[2] = d2; hdst[3] = d3;
            }
            __syncthreads();   // barrier #1: h_sm staged

            // Matvec: gates = Wc @ h (register weights, smem h, packed f32x2 FMA)
            a0 = make_float2(0.f, 0.f);
            a1 = make_float2(0.f, 0.f);
#pragma unroll
            for (int i = 0; i < 8; i++) {
                float4 hv = h4[i * 32 + l];
                a0 = ffma2(make_float2(wc0[i].x, wc0[i].y), make_float2(hv.x, hv.y), a0);
                a0 = ffma2(make_float2(wc0[i].z, wc0[i].w), make_float2(hv.z, hv.w), a0);
                a1 = ffma2(make_float2(wc1[i].x, wc1[i].y), make_float2(hv.x, hv.y), a1);
                a1 = ffma2(make_float2(wc1[i].z, wc1[i].w), make_float2(hv.z, hv.w), a1);
            }
        }

        // Warp reductions: two interleaved 5-level butterflies.
        float s0 = a0.x + a0.y;
        float s1 = a1.x + a1.y;
#pragma unroll
        for (int d = 16; d > 0; d >>= 1) {
            s0 += __shfl_xor_sync(0xffffffffu, s0, d);
            s1 += __shfl_xor_sync(0xffffffffu, s1, d);
        }
        // Per-warp uniform nonlinearity in parallel (lanes 0/1 of all warps).
        if (l < 2) {
            float x  = (l == 0) ? (s0 + bc0) : (s1 + bc1);
            float nl = warp_is_tanh ? ftanh(x) : fsigm(x);
            gates_sm[r0 + l] = nl;
        }
        __syncthreads();       // barrier #2: gates ready

        // Combine + release-ordered publish: warp 0 only.
        if (w == 0) {
            if (l < 8) {
                float gi = gates_sm[l];
                float gf = gates_sm[8 + l];
                float gg = gates_sm[16 + l];
                float go = gates_sm[24 + l];
                c = gf * c + gi * gg;
                float h = go * ftanh(c);
                hpub_sm[l] = h;
                g_hs[(size_t)t * H + b * 8 + l] = h;   // history for MLP
            }
            __syncwarp();
            if (l == 0) {
                const unsigned long long* hp =
                    reinterpret_cast<const unsigned long long*>(hpub_sm);
                unsigned long long* dst = g_pub[t & 1][b];
                st_relaxed_2u64(dst,     hp[0], hp[1]);
                st_relaxed_2u64(dst + 2, hp[2], hp[3]);
                st_release_u64(&g_ptag[t & 1][b], (unsigned long long)(t + 1));
            }
        }
        // No trailing barrier: t+1 staging (writes h_sm) happens only after
        // barrier #1 of t+1... wait -- staging precedes #1. Ordering argument:
        // stagers (tid<128) reach t+1 staging only after passing barrier #2 of
        // step t, by which point ALL warps finished their h_sm matvec reads
        // (reads precede the gates_sm writes that precede #2). gates_sm reuse
        // at t+1 is written only after barrier #1 of t+1, which warp 0 joins
        // after finishing its gates_sm reads here. Both hazards ordered.
    }
}

// ---------- per-timestep MLP head (R1's proven version) ----------

__global__ void __launch_bounds__(128)
mlp_kernel(const float* __restrict__ W1, const float* __restrict__ b1,
           const float* __restrict__ W2, const float* __restrict__ b2,
           const float* __restrict__ W3, const float* __restrict__ b3,
           float* __restrict__ out)
{
    __shared__ __align__(16) float h_sm[H];
    __shared__ float a1s[32];
    __shared__ float a2s[32];

    const int t   = blockIdx.x;
    const int tid = threadIdx.x;
    const int w   = tid >> 5;
    const int l   = tid & 31;

    const float4* src = reinterpret_cast<const float4*>(g_hs + (size_t)t * H);
    reinterpret_cast<float4*>(h_sm)[tid]       = src[tid];
    reinterpret_cast<float4*>(h_sm)[128 + tid] = src[128 + tid];
    __syncthreads();

    // Layer 1: 32 outputs; warp w computes outputs [8w, 8w+8), lanes stride columns.
    float acc[8];
#pragma unroll
    for (int oo = 0; oo < 8; oo++) acc[oo] = 0.0f;
#pragma unroll 4
    for (int i = 0; i < 32; i++) {
        float hv = h_sm[i * 32 + l];
#pragma unroll
        for (int oo = 0; oo < 8; oo++) {
            acc[oo] = fmaf(W1[(w * 8 + oo) * H + i * 32 + l], hv, acc[oo]);
        }
    }
#pragma unroll
    for (int oo = 0; oo < 8; oo++) {
#pragma unroll
        for (int d = 16; d > 0; d >>= 1)
            acc[oo] += __shfl_xor_sync(0xffffffffu, acc[oo], d);
    }
    if (l == 0) {
#pragma unroll
        for (int oo = 0; oo < 8; oo++) {
            int o = w * 8 + oo;
            a1s[o] = fmaxf(acc[oo] + b1[o], 0.0f);
        }
    }
    __syncthreads();

    // Layer 2: 32x32
    if (tid < 32) {
        float a = b2[tid];
#pragma unroll
        for (int k = 0; k < 32; k++) a = fmaf(W2[tid * 32 + k], a1s[k], a);
        a2s[tid] = fmaxf(a, 0.0f);
    }
    __syncthreads();

    // Layer 3: 64x32 -> output
    if (tid < KOUT) {
        float a = b3[tid];
#pragma unroll
        for (int k = 0; k < 32; k++) a = fmaf(W3[tid * 32 + k], a2s[k], a);
        out[(size_t)t * KOUT + tid] = a;
    }
}

// ---------- launch ----------

extern "C" void kernel_launch(void* const* d_in, const int* in_sizes, int n_in,
                              void* d_out, int out_size)
{
    const float* z   = (const float*)d_in[0];
    const float* Wih = (const float*)d_in[1];
    const float* Whh = (const float*)d_in[2];
    const float* bih = (const float*)d_in[3];
    const float* bhh = (const float*)d_in[4];
    const float* W1  = (const float*)d_in[5];
    const float* b1  = (const float*)d_in[6];
    const float* W2  = (const float*)d_in[7];
    const float* b2  = (const float*)d_in[8];
    const float* W3  = (const float*)d_in[9];
    const float* b3  = (const float*)d_in[10];
    float* out = (float*)d_out;

    lstm_kernel<<<NBLK, NTHR>>>(z, Wih, Whh, bih, bhh);
    mlp_kernel<<<TSTEPS, 128>>>(W1, b1, W2, b2, W3, b3, out);
}

// round 13
// speedup vs baseline: 2.7686x; 2.7686x over previous
#include <cuda_runtime.h>
#include <math.h>

#define H      1024
#define TSTEPS 2048
#define KOUT   64
#define NBLK   128     // = H/8, one block per 8 hidden units
#define NTHR   512     // 16 warps = 4 row-groups x 4 col-groups

// Scratch (device globals: no allocation allowed in kernel_launch)
__device__ float g_hs[TSTEPS * H];   // h_t history (consumed by the MLP pass)
// Broadcast ping-pong: 2 slots x 1024 u64 packets {tag:32 | h_bits:32}.
// STRONG (relaxed.gpu) ops: single-copy atomic per 8B element (PTX memory
// model). Data+tag in ONE word -> no fence anywhere in the hot loop
// (R12 proved gpu-scope fences emit CCTL.IVALL L1-flushes: 4x regression).
// tag = step+1: zero-init never matches; cross-replay residue is benign
// (identical deterministic values).
__device__ __align__(16) unsigned long long g_bc64[2 * 1024];

// ---------- helpers ----------

__device__ __forceinline__ float2 ffma2(float2 a, float2 b, float2 c) {
    unsigned long long ua = *reinterpret_cast<unsigned long long*>(&a);
    unsigned long long ub = *reinterpret_cast<unsigned long long*>(&b);
    unsigned long long uc = *reinterpret_cast<unsigned long long*>(&c);
    unsigned long long ud;
    asm("fma.rn.f32x2 %0, %1, %2, %3;" : "=l"(ud) : "l"(ua), "l"(ub), "l"(uc));
    return *reinterpret_cast<float2*>(&ud);
}

__device__ __forceinline__ void ld_relaxed_2u64(const unsigned long long* p,
                                                unsigned long long& a,
                                                unsigned long long& b) {
    asm volatile("ld.relaxed.gpu.global.v2.u64 {%0,%1}, [%2];"
                 : "=l"(a), "=l"(b) : "l"(p) : "memory");
}

__device__ __forceinline__ void st_relaxed_u64(unsigned long long* p, unsigned long long v) {
    asm volatile("st.relaxed.gpu.global.u64 [%0], %1;" :: "l"(p), "l"(v) : "memory");
}

// MUFU-approx sigmoid/tanh (~1e-6 rel/op). VALIDATED in R10/R11 under the
// strong transport: full 2048-step recurrence at rel_err 2.03e-7.
__device__ __forceinline__ float fsigm(float x) {
    float e, r;
    asm("ex2.approx.f32 %0, %1;" : "=f"(e) : "f"(-1.4426950408889634f * x));
    asm("rcp.approx.f32 %0, %1;" : "=f"(r) : "f"(1.0f + e));
    return r;
}
__device__ __forceinline__ float ftanh(float x) {
    return fmaf(2.0f, fsigm(2.0f * x), -1.0f);
}

// ---------- persistent LSTM recurrence ----------
//
// Block b owns hidden units [8b, 8b+8). COLUMN-SPLIT matvec: warp w is
// (row-group g = w>>2, col-group cg = w&3) and computes local gate rows
// [8g, 8g+8) over columns [256cg, 256cg+256). Each thread loads its 8-col h
// slice once (2 LDS.128) and reuses it for all 8 rows -> smem traffic
// 16KB/step (4x less than 2-rows/warp). Weights Wc = Wih+Whh in registers
// (8 rows x 2 float4 = 64 floats/thread, same as R9's proven sweet spot).
// Local row r -> global gate row (r>>3)*H + b*8 + (r&7); gate order i,f,g,o.
// Cross-SM sync: R9-proven self-tagged strong packets, 2-deep 16B polls.

__global__ void __launch_bounds__(NTHR, 1)
lstm_kernel(const float* __restrict__ z,
            const float* __restrict__ Wih,
            const float* __restrict__ Whh,
            const float* __restrict__ bih,
            const float* __restrict__ bhh)
{
    __shared__ __align__(16) float h_sm[H];
    __shared__ __align__(16) float part_sm[32][4];  // per-(row, col-group) partials
    __shared__ float bias_sm[32];                   // combined per-row bias

    const int tid = threadIdx.x;
    const int b   = blockIdx.x;
    const int w   = tid >> 5;
    const int l   = tid & 31;
    const int g   = w >> 2;     // row-group: gate octet
    const int cg  = w & 3;      // col-group: columns [256cg, 256cg+256)
    const int hidx = 64 * cg + 2 * l;   // this thread's h float4 index (2 consecutive)

    // Stage z into h_sm (input of step 0).
    reinterpret_cast<float2*>(h_sm)[tid] = reinterpret_cast<const float2*>(z)[tid];
    __syncthreads();

    const float4* Wih4 = reinterpret_cast<const float4*>(Wih);
    const float4* Whh4 = reinterpret_cast<const float4*>(Whh);
    const float4* h4   = reinterpret_cast<const float4*>(h_sm);

    // Prologue: load Wih/Whh once; compute step-0 partials with Wih (h0=0),
    // keep Wc = Wih + Whh resident in registers for all later steps.
    float4 wc[8][2];
    float2 acc[8];
    {
        float4 ha = h4[hidx], hb = h4[hidx + 1];
#pragma unroll
        for (int j = 0; j < 8; j++) {
            const int G  = g * H + b * 8 + j;           // global gate row
            const int ci = G * (H / 4) + hidx;
            float4 wi0 = Wih4[ci], wi1 = Wih4[ci + 1];
            float4 wh0 = Whh4[ci], wh1 = Whh4[ci + 1];
            float2 a = make_float2(0.f, 0.f);
            a = ffma2(make_float2(wi0.x, wi0.y), make_float2(ha.x, ha.y), a);
            a = ffma2(make_float2(wi0.z, wi0.w), make_float2(ha.z, ha.w), a);
            a = ffma2(make_float2(wi1.x, wi1.y), make_float2(hb.x, hb.y), a);
            a = ffma2(make_float2(wi1.z, wi1.w), make_float2(hb.z, hb.w), a);
            acc[j] = a;
            wc[j][0] = make_float4(wi0.x + wh0.x, wi0.y + wh0.y, wi0.z + wh0.z, wi0.w + wh0.w);
            wc[j][1] = make_float4(wi1.x + wh1.x, wi1.y + wh1.y, wi1.z + wh1.z, wi1.w + wh1.w);
        }
    }
    if (tid < 32) {
        const int Gt = (tid >> 3) * H + b * 8 + (tid & 7);
        bias_sm[tid] = bih[Gt] + bhh[Gt];
    }
    __syncthreads();

    float c = 0.0f;   // cell state: live only in warp 0, lanes 0..7

    for (int t = 0; t < TSTEPS; t++) {
        if (t > 0) {
            // Poll own two packets of h_{t-1}: 2-deep pipelined 16B strong
            // loads (R9-proven).
            const unsigned want = (unsigned)t;            // tag of step t-1
            const unsigned long long* s = g_bc64 + ((t - 1) & 1) * 1024 + 2 * tid;
            unsigned long long p0, p1, q0, q1;
            for (;;) {
                ld_relaxed_2u64(s, p0, p1);
                ld_relaxed_2u64(s, q0, q1);
                if ((unsigned)(p0 >> 32) == want && (unsigned)(p1 >> 32) == want) break;
                if ((unsigned)(q0 >> 32) == want && (unsigned)(q1 >> 32) == want) {
                    p0 = q0; p1 = q1; break;
                }
            }
            reinterpret_cast<float2*>(h_sm)[tid] =
                make_float2(__uint_as_float((unsigned)p0), __uint_as_float((unsigned)p1));
            __syncthreads();   // barrier #1: h_sm staged

            // Column-split matvec: 2 LDS.128 of h reused across 8 rows.
            float4 ha = h4[hidx], hb = h4[hidx + 1];
            float2 hal = make_float2(ha.x, ha.y), hah = make_float2(ha.z, ha.w);
            float2 hbl = make_float2(hb.x, hb.y), hbh = make_float2(hb.z, hb.w);
#pragma unroll
            for (int j = 0; j < 8; j++) {
                float2 a = make_float2(0.f, 0.f);
                a = ffma2(make_float2(wc[j][0].x, wc[j][0].y), hal, a);
                a = ffma2(make_float2(wc[j][0].z, wc[j][0].w), hah, a);
                a = ffma2(make_float2(wc[j][1].x, wc[j][1].y), hbl, a);
                a = ffma2(make_float2(wc[j][1].z, wc[j][1].w), hbh, a);
                acc[j] = a;
            }
        }

        // Butterfly-reduce 8 row partials (8 independent 5-level chains).
        float s0 = acc[0].x + acc[0].y, s1 = acc[1].x + acc[1].y;
        float s2 = acc[2].x + acc[2].y, s3 = acc[3].x + acc[3].y;
        float s4 = acc[4].x + acc[4].y, s5 = acc[5].x + acc[5].y;
        float s6 = acc[6].x + acc[6].y, s7 = acc[7].x + acc[7].y;
#pragma unroll
        for (int d = 16; d > 0; d >>= 1) {
            s0 += __shfl_xor_sync(0xffffffffu, s0, d);
            s1 += __shfl_xor_sync(0xffffffffu, s1, d);
            s2 += __shfl_xor_sync(0xffffffffu, s2, d);
            s3 += __shfl_xor_sync(0xffffffffu, s3, d);
            s4 += __shfl_xor_sync(0xffffffffu, s4, d);
            s5 += __shfl_xor_sync(0xffffffffu, s5, d);
            s6 += __shfl_xor_sync(0xffffffffu, s6, d);
            s7 += __shfl_xor_sync(0xffffffffu, s7, d);
        }
        // Lane j writes row (8g+j)'s partial for this col-group.
        if (l == 0) part_sm[8 * g + 0][cg] = s0;
        if (l == 1) part_sm[8 * g + 1][cg] = s1;
        if (l == 2) part_sm[8 * g + 2][cg] = s2;
        if (l == 3) part_sm[8 * g + 3][cg] = s3;
        if (l == 4) part_sm[8 * g + 4][cg] = s4;
        if (l == 5) part_sm[8 * g + 5][cg] = s5;
        if (l == 6) part_sm[8 * g + 6][cg] = s6;
        if (l == 7) part_sm[8 * g + 7][cg] = s7;
        __syncthreads();   // barrier #2: partials ready

        // Tail: warp 0 sums 4 partials/row, applies per-row nonlinearity in
        // parallel (approx, validated), gathers, updates c/h, publishes.
        if (w == 0) {
            float4 p = *reinterpret_cast<float4*>(part_sm[l]);
            float x  = (p.x + p.y) + (p.z + p.w) + bias_sm[l];
            float nl = (l >= 16 && l < 24) ? ftanh(x) : fsigm(x);
            const int k = l & 7;
            float gi = __shfl_sync(0xffffffffu, nl, k);
            float gf = __shfl_sync(0xffffffffu, nl, 8 + k);
            float gg = __shfl_sync(0xffffffffu, nl, 16 + k);
            float go = __shfl_sync(0xffffffffu, nl, 24 + k);
            if (l < 8) {
                c = gf * c + gi * gg;
                float h = go * ftanh(c);

                unsigned long long pkt =
                    ((unsigned long long)(unsigned)(t + 1) << 32) |
                    (unsigned long long)__float_as_uint(h);
                st_relaxed_u64(g_bc64 + (t & 1) * 1024 + b * 8 + l, pkt);
                g_hs[(size_t)t * H + b * 8 + l] = h;   // history for MLP
            }
        }
        // Hold all warps until the local publish is issued (R9-proven):
        // prevents stale-poll flooding of L2 while producers commit stores.
        __syncthreads();
    }
}

// ---------- per-timestep MLP head (R1's proven version) ----------

__global__ void __launch_bounds__(128)
mlp_kernel(const float* __restrict__ W1, const float* __restrict__ b1,
           const float* __restrict__ W2, const float* __restrict__ b2,
           const float* __restrict__ W3, const float* __restrict__ b3,
           float* __restrict__ out)
{
    __shared__ __align__(16) float h_sm[H];
    __shared__ float a1s[32];
    __shared__ float a2s[32];

    const int t   = blockIdx.x;
    const int tid = threadIdx.x;
    const int w   = tid >> 5;
    const int l   = tid & 31;

    const float4* src = reinterpret_cast<const float4*>(g_hs + (size_t)t * H);
    reinterpret_cast<float4*>(h_sm)[tid]       = src[tid];
    reinterpret_cast<float4*>(h_sm)[128 + tid] = src[128 + tid];
    __syncthreads();

    // Layer 1: 32 outputs; warp w computes outputs [8w, 8w+8), lanes stride columns.
    float acc[8];
#pragma unroll
    for (int oo = 0; oo < 8; oo++) acc[oo] = 0.0f;
#pragma unroll 4
    for (int i = 0; i < 32; i++) {
        float hv = h_sm[i * 32 + l];
#pragma unroll
        for (int oo = 0; oo < 8; oo++) {
            acc[oo] = fmaf(W1[(w * 8 + oo) * H + i * 32 + l], hv, acc[oo]);
        }
    }
#pragma unroll
    for (int oo = 0; oo < 8; oo++) {
#pragma unroll
        for (int d = 16; d > 0; d >>= 1)
            acc[oo] += __shfl_xor_sync(0xffffffffu, acc[oo], d);
    }
    if (l == 0) {
#pragma unroll
        for (int oo = 0; oo < 8; oo++) {
            int o = w * 8 + oo;
            a1s[o] = fmaxf(acc[oo] + b1[o], 0.0f);
        }
    }
    __syncthreads();

    // Layer 2: 32x32
    if (tid < 32) {
        float a = b2[tid];
#pragma unroll
        for (int k = 0; k < 32; k++) a = fmaf(W2[tid * 32 + k], a1s[k], a);
        a2s[tid] = fmaxf(a, 0.0f);
    }
    __syncthreads();

    // Layer 3: 64x32 -> output
    if (tid < KOUT) {
        float a = b3[tid];
#pragma unroll
        for (int k = 0; k < 32; k++) a = fmaf(W3[tid * 32 + k], a2s[k], a);
        out[(size_t)t * KOUT + tid] = a;
    }
}

// ---------- launch ----------

extern "C" void kernel_launch(void* const* d_in, const int* in_sizes, int n_in,
                              void* d_out, int out_size)
{
    const float* z   = (const float*)d_in[0];
    const float* Wih = (const float*)d_in[1];
    const float* Whh = (const float*)d_in[2];
    const float* bih = (const float*)d_in[3];
    const float* bhh = (const float*)d_in[4];
    const float* W1  = (const float*)d_in[5];
    const float* b1  = (const float*)d_in[6];
    const float* W2  = (const float*)d_in[7];
    const float* b2  = (const float*)d_in[8];
    const float* W3  = (const float*)d_in[9];
    const float* b3  = (const float*)d_in[10];
    float* out = (float*)d_out;

    lstm_kernel<<<NBLK, NTHR>>>(z, Wih, Whh, bih, bhh);
    mlp_kernel<<<TSTEPS, 128>>>(W1, b1, W2, b2, W3, b3, out);
}